// round 7
// baseline (speedup 1.0000x reference)
#include <cuda_runtime.h>
#include <cstdint>
#include <cstddef>

#define DH __host__ __device__

// ---------------- compile-time DCT constants ----------------
DH constexpr double tcos_core(double x) {
    double x2 = x * x, t = 1.0, s = 1.0;
    for (int i = 1; i <= 12; i++) { t *= -x2 / (double)((2 * i - 1) * (2 * i)); s += t; }
    return s;
}
DH constexpr double dctcosd(int f, int p) {
    int m = ((2 * p + 1) * f) % 128;
    double sg = 1.0;
    if (m > 64) m = 128 - m;
    if (m > 32) { sg = -1.0; m = 64 - m; }
    const double PI = 3.14159265358979323846264338327950288;
    return sg * tcos_core((double)m * PI / 64.0);
}
DH constexpr double rsqrt2c() {
    double g = 0.7;
    for (int i = 0; i < 50; i++) g = 0.5 * (g + 0.5 / g);
    return g;
}
DH constexpr float c1val(int v, int y) {  // vertical: fold c_v
    return (float)(dctcosd(v, y) * (v == 0 ? rsqrt2c() : 1.0));
}
DH constexpr float c2val(int u, int x) {  // horizontal: fold c_u and 2/32
    return (float)(dctcosd(u, x) * (u == 0 ? rsqrt2c() : 1.0) * (2.0 / 32.0));
}

// ---------------- stage 1: vertical butterfly DCT, single RGB plane, 32 accs ----------------
template <int P, int V> struct S1V {
    static __device__ __forceinline__ void run(float s, float d, float (&a)[32]) {
        a[2 * V]     = fmaf(s, c1val(2 * V,     P), a[2 * V]);
        a[2 * V + 1] = fmaf(d, c1val(2 * V + 1, P), a[2 * V + 1]);
        S1V<P, V + 1>::run(s, d, a);
    }
};
template <int P> struct S1V<P, 16> {
    static __device__ __forceinline__ void run(float, float, float (&)[32]) {}
};
template <int P> struct S1P {
    static __device__ __forceinline__ void run(const float* __restrict__ q, float (&a)[32]) {
        float lo = q[P * 512], hi = q[(31 - P) * 512];
        S1V<P, 0>::run(lo + hi, lo - hi, a);
        S1P<P + 1>::run(q, a);
    }
};
template <> struct S1P<16> {
    static __device__ __forceinline__ void run(const float* __restrict__, float (&)[32]) {}
};

// ---------------- stage 2: horizontal butterfly DCT with inline RGB->YCbCr ----------------
// C=0: 2*Y (DC "-1" fixed at end); C=1: Cb'; C=2: Cr'.
template <int C>
__device__ __forceinline__ float mixc(float r, float g, float b) {
    float y0 = fmaf(0.299f, r, fmaf(0.587f, g, 0.114f * b));
    if (C == 0) return 2.0f * y0;
    if (C == 1) return (b - y0) * 1.128f;
    return (r - y0) * 1.426f;
}

template <int P, int J> struct S2U {
    static __device__ __forceinline__ void run(float s, float d, float (&a)[32]) {
        a[2 * J]     = fmaf(s, c2val(2 * J,     P), a[2 * J]);
        a[2 * J + 1] = fmaf(d, c2val(2 * J + 1, P), a[2 * J + 1]);
        S2U<P, J + 1>::run(s, d, a);
    }
};
template <int P> struct S2U<P, 16> {
    static __device__ __forceinline__ void run(float, float, float (&)[32]) {}
};
template <int C, int P> struct S2P {
    static __device__ __forceinline__ void run(const float* __restrict__ tr,
                                               const float* __restrict__ tg,
                                               const float* __restrict__ tb,
                                               float (&a)[32]) {
        float lo = mixc<C>(tr[P],      tg[P],      tb[P]);
        float hi = mixc<C>(tr[31 - P], tg[31 - P], tb[31 - P]);
        S2U<P, 0>::run(lo + hi, lo - hi, a);
        S2P<C, P + 1>::run(tr, tg, tb, a);
    }
};
template <int C> struct S2P<C, 16> {
    static __device__ __forceinline__ void run(const float* __restrict__, const float* __restrict__,
                                               const float* __restrict__, float (&)[32]) {}
};

// ---------------- permutation derivation from the kernels input ----------------
__device__ int g_pos[1024];  // pos[v*32+u] = output channel index k

__device__ __forceinline__ unsigned long long lanemax_ull(unsigned long long k) {
    #pragma unroll
    for (int o = 16; o; o >>= 1) {
        unsigned long long other = __shfl_xor_sync(0xffffffffu, k, o);
        if (other > k) k = other;
    }
    return k;
}

__global__ void perm_kernel(const float* __restrict__ ker) {
    int k = blockIdx.x * 8 + (threadIdx.x >> 5);
    int f = threadIdx.x & 31;
    const float* K = ker + (size_t)k * 1024;
    float s = 0.f, t = 0.f;
    #pragma unroll
    for (int x = 0; x < 32; x++) {
        float c = cospif((float)((2 * x + 1) * f) * (1.0f / 64.0f));
        s = fmaf(K[x],      c, s);
        t = fmaf(K[x * 32], c, t);
    }
    unsigned long long ks = (((unsigned long long)__float_as_uint(fabsf(s))) << 32) | (unsigned)f;
    unsigned long long kt = (((unsigned long long)__float_as_uint(fabsf(t))) << 32) | (unsigned)f;
    ks = lanemax_ull(ks);
    kt = lanemax_ull(kt);
    if (f == 0) {
        g_pos[(int)(kt & 31u) * 32 + (int)(ks & 31u)] = k;
    }
}

// ---------------- main fused kernel ----------------
// Grid: (ng=4, m=16, b=32). CTA = 384 threads, one 32-row x 128-col strip (4 blocks).
// tmp planes: [c][v][x] at c*4224 + v*132 + (x/32)*33 + (x%32); c = R,G,B DCT_v
// (color mixing deferred to stage 2 via linearity).
static constexpr int PLANE_FLOATS = 32 * 132;          // 4224
static constexpr int TMP_FLOATS = 3 * PLANE_FLOATS;    // 12672 floats = 50688 B

__global__ void __launch_bounds__(384, 2)
dct_main(const float* __restrict__ rgb, float* __restrict__ out) {
    extern __shared__ float tmp[];
    __shared__ int pos_s[1024];

    const int tid = threadIdx.x;
    const int ng = blockIdx.x;   // n-group (4 blocks each)
    const int m  = blockIdx.y;   // block row
    const int b  = blockIdx.z;   // batch

    for (int i = tid; i < 1024; i += 384) pos_s[i] = g_pos[i];

    // ---- stage 1: per-RGB-plane vertical butterfly DCT. thread = (c, col). ----
    {
        const int c = tid >> 7;          // 0..2 (R,G,B)
        const int col = tid & 127;
        const size_t plane = (size_t)512 * 512;
        const float* q = rgb + (size_t)b * 3 * plane + (size_t)c * plane
                             + (size_t)(m * 32) * 512 + ng * 128 + col;

        float acc[32];
        #pragma unroll
        for (int v = 0; v < 32; v++) acc[v] = 0.f;

        S1P<0>::run(q, acc);

        float* tb = tmp + c * PLANE_FLOATS + (col >> 5) * 33 + (col & 31);
        #pragma unroll
        for (int v = 0; v < 32; v++)
            tb[v * 132] = acc[v];
    }
    __syncthreads();

    // ---- stage 2: horizontal butterfly DCT + inline color mix. thread = (c, v, nblk). ----
    {
        const int c = tid >> 7;             // 0..2 (Y,Cb,Cr)
        const int rem = tid & 127;
        const int v = rem >> 2;             // 0..31
        const int nblk = rem & 3;           // 0..3
        const int off = v * 132 + nblk * 33;
        const float* tr = tmp + off;
        const float* tg = tmp + PLANE_FLOATS + off;
        const float* tb = tmp + 2 * PLANE_FLOATS + off;

        float a2[32];
        #pragma unroll
        for (int u = 0; u < 32; u++) a2[u] = 0.f;

        if (c == 0)      S2P<0, 0>::run(tr, tg, tb, a2);
        else if (c == 1) S2P<1, 0>::run(tr, tg, tb, a2);
        else             S2P<2, 0>::run(tr, tg, tb, a2);

        if (tid < 4) a2[0] -= 32.0f;   // c==0 && v==0: DC term of the "-1" offset

        const int n = ng * 4 + nblk;
        float* obc = out + (size_t)b * 3072 * 256 + (size_t)c * 1024 * 256 + m * 16 + n;
        const int* pv = pos_s + v * 32;
        #pragma unroll
        for (int u = 0; u < 32; u++) {
            obc[(size_t)pv[u] * 256] = a2[u];  // bijective: every output written once
        }
    }
}

// ---------------- launch ----------------
extern "C" void kernel_launch(void* const* d_in, const int* in_sizes, int n_in,
                              void* d_out, int out_size) {
    const float* rgb = (const float*)d_in[0];
    const float* ker = (const float*)d_in[1];
    float* out = (float*)d_out;

    perm_kernel<<<128, 256>>>(ker);

    cudaFuncSetAttribute(dct_main, cudaFuncAttributeMaxDynamicSharedMemorySize,
                         TMP_FLOATS * (int)sizeof(float));
    dct_main<<<dim3(4, 16, 32), 384, TMP_FLOATS * (int)sizeof(float)>>>(rgb, out);
}

// round 8
// speedup vs baseline: 1.2132x; 1.2132x over previous
#include <cuda_runtime.h>
#include <cuda_fp16.h>
#include <cstdint>
#include <cstddef>

#define DH __host__ __device__

// ---------------- compile-time DCT constants ----------------
DH constexpr double tcos_core(double x) {
    double x2 = x * x, t = 1.0, s = 1.0;
    for (int i = 1; i <= 12; i++) { t *= -x2 / (double)((2 * i - 1) * (2 * i)); s += t; }
    return s;
}
DH constexpr double dctcosd(int f, int p) {
    int m = ((2 * p + 1) * f) % 128;
    double sg = 1.0;
    if (m > 64) m = 128 - m;
    if (m > 32) { sg = -1.0; m = 64 - m; }
    const double PI = 3.14159265358979323846264338327950288;
    return sg * tcos_core((double)m * PI / 64.0);
}
DH constexpr double rsqrt2c() {
    double g = 0.7;
    for (int i = 0; i < 50; i++) g = 0.5 * (g + 0.5 / g);
    return g;
}
DH constexpr float c1val(int v, int y) {  // vertical: fold c_v
    return (float)(dctcosd(v, y) * (v == 0 ? rsqrt2c() : 1.0));
}
DH constexpr float c2val(int u, int x) {  // horizontal: fold c_u and 2/32
    return (float)(dctcosd(u, x) * (u == 0 ? rsqrt2c() : 1.0) * (2.0 / 32.0));
}

// ---------------- stage 1: vertical butterfly DCT, single RGB plane, 32 accs ----------------
template <int P, int V> struct S1V {
    static __device__ __forceinline__ void run(float s, float d, float (&a)[32]) {
        a[2 * V]     = fmaf(s, c1val(2 * V,     P), a[2 * V]);
        a[2 * V + 1] = fmaf(d, c1val(2 * V + 1, P), a[2 * V + 1]);
        S1V<P, V + 1>::run(s, d, a);
    }
};
template <int P> struct S1V<P, 16> {
    static __device__ __forceinline__ void run(float, float, float (&)[32]) {}
};
template <int P> struct S1P {
    static __device__ __forceinline__ void run(const float* __restrict__ q, float (&a)[32]) {
        float lo = q[P * 512], hi = q[(31 - P) * 512];
        S1V<P, 0>::run(lo + hi, lo - hi, a);
        S1P<P + 1>::run(q, a);
    }
};
template <> struct S1P<16> {
    static __device__ __forceinline__ void run(const float* __restrict__, float (&)[32]) {}
};

// ---------------- stage 2: horizontal butterfly DCT from fp16 plane, 32 accs ----------------
template <int P, int J> struct S2U {
    static __device__ __forceinline__ void run(float s, float d, float (&a)[32]) {
        a[2 * J]     = fmaf(s, c2val(2 * J,     P), a[2 * J]);
        a[2 * J + 1] = fmaf(d, c2val(2 * J + 1, P), a[2 * J + 1]);
        S2U<P, J + 1>::run(s, d, a);
    }
};
template <int P> struct S2U<P, 16> {
    static __device__ __forceinline__ void run(float, float, float (&)[32]) {}
};
template <int P> struct S2P {
    static __device__ __forceinline__ void run(const __half* __restrict__ t, float (&a)[32]) {
        float lo = __half2float(t[P]), hi = __half2float(t[31 - P]);
        S2U<P, 0>::run(lo + hi, lo - hi, a);
        S2P<P + 1>::run(t, a);
    }
};
template <> struct S2P<16> {
    static __device__ __forceinline__ void run(const __half* __restrict__, float (&)[32]) {}
};

// ---------------- permutation derivation from the kernels input ----------------
__device__ int g_pos[1024];  // pos[v*32+u] = output channel index k

__device__ __forceinline__ unsigned long long lanemax_ull(unsigned long long k) {
    #pragma unroll
    for (int o = 16; o; o >>= 1) {
        unsigned long long other = __shfl_xor_sync(0xffffffffu, k, o);
        if (other > k) k = other;
    }
    return k;
}

__global__ void perm_kernel(const float* __restrict__ ker) {
    int k = blockIdx.x * 8 + (threadIdx.x >> 5);
    int f = threadIdx.x & 31;
    const float* K = ker + (size_t)k * 1024;
    float s = 0.f, t = 0.f;
    #pragma unroll
    for (int x = 0; x < 32; x++) {
        float c = cospif((float)((2 * x + 1) * f) * (1.0f / 64.0f));
        s = fmaf(K[x],      c, s);
        t = fmaf(K[x * 32], c, t);
    }
    unsigned long long ks = (((unsigned long long)__float_as_uint(fabsf(s))) << 32) | (unsigned)f;
    unsigned long long kt = (((unsigned long long)__float_as_uint(fabsf(t))) << 32) | (unsigned)f;
    ks = lanemax_ull(ks);
    kt = lanemax_ull(kt);
    if (f == 0) {
        g_pos[(int)(kt & 31u) * 32 + (int)(ks & 31u)] = k;
    }
}

// ---------------- main fused kernel ----------------
// Grid: (ng=2, m=16, b=32). CTA = 256 threads, one 32-row x 256-col strip (8 blocks).
// tmp (fp16) planes: [c][v][x] at c*8448 + v*264 + (x/32)*33 + (x%32) halfs.
// Stage 1 writes R,G,B vertical-DCT planes; mix pass converts in place to
// (2Y, Cb', Cr') by linearity; stage 2 reads a single plane per task.
static constexpr int PLANE_HALFS = 32 * 264;           // 8448
static constexpr int TMP_HALFS = 3 * PLANE_HALFS;      // 25344 halfs = 50688 B
static constexpr int PLANE_H2 = PLANE_HALFS / 2;       // 4224

__global__ void __launch_bounds__(256, 4)
dct_main(const float* __restrict__ rgb, float* __restrict__ out) {
    extern __shared__ __half tmp[];
    __shared__ int pos_s[1024];

    const int tid = threadIdx.x;
    const int ng = blockIdx.x;   // n-group (8 blocks each)
    const int m  = blockIdx.y;   // block row
    const int b  = blockIdx.z;   // batch

    #pragma unroll
    for (int i = 0; i < 4; i++) pos_s[i * 256 + tid] = g_pos[i * 256 + tid];

    // ---- stage 1: per-plane vertical butterfly DCT. thread = col, loop c. ----
    {
        const size_t plane = (size_t)512 * 512;
        const float* q0 = rgb + (size_t)b * 3 * plane + (size_t)(m * 32) * 512 + ng * 256 + tid;
        const int go = (tid >> 5) * 33 + (tid & 31);

        #pragma unroll 1
        for (int c = 0; c < 3; c++) {
            const float* q = q0 + (size_t)c * plane;
            float acc[32];
            #pragma unroll
            for (int v = 0; v < 32; v++) acc[v] = 0.f;

            S1P<0>::run(q, acc);

            __half* tb = tmp + c * PLANE_HALFS + go;
            #pragma unroll
            for (int v = 0; v < 32; v++)
                tb[v * 264] = __float2half_rn(acc[v]);
        }
    }
    __syncthreads();

    // ---- mix pass (half2-vectorized): RGB planes -> (2Y, Cb', Cr') in place ----
    {
        __half2* t2 = reinterpret_cast<__half2*>(tmp);
        #pragma unroll 1
        for (int i = tid; i < PLANE_H2; i += 256) {
            float2 r2 = __half22float2(t2[i]);
            float2 g2 = __half22float2(t2[PLANE_H2 + i]);
            float2 b2 = __half22float2(t2[2 * PLANE_H2 + i]);
            float y0x = fmaf(0.299f, r2.x, fmaf(0.587f, g2.x, 0.114f * b2.x));
            float y0y = fmaf(0.299f, r2.y, fmaf(0.587f, g2.y, 0.114f * b2.y));
            t2[i]              = __floats2half2_rn(2.0f * y0x, 2.0f * y0y);
            t2[PLANE_H2 + i]   = __floats2half2_rn((b2.x - y0x) * 1.128f, (b2.y - y0y) * 1.128f);
            t2[2 * PLANE_H2 + i] = __floats2half2_rn((r2.x - y0x) * 1.426f, (r2.y - y0y) * 1.426f);
        }
    }
    __syncthreads();

    // ---- stage 2: horizontal butterfly DCT. thread = (v, nblk), loop c. ----
    {
        const int v = tid >> 3, nblk = tid & 7;
        const int n = ng * 8 + nblk;
        float* ob = out + (((size_t)b * 3072) * 16 + m) * 16 + n;
        const int* pv = pos_s + v * 32;
        const __half* tbase = tmp + v * 264 + nblk * 33;

        #pragma unroll 1
        for (int c = 0; c < 3; c++) {
            float a2[32];
            #pragma unroll
            for (int u = 0; u < 32; u++) a2[u] = 0.f;

            S2P<0>::run(tbase + c * PLANE_HALFS, a2);

            if (c == 0 && v == 0) a2[0] -= 32.0f;   // DC term of the "-1" offset

            float* obc = ob + (size_t)c * 1024 * 256;
            #pragma unroll
            for (int u = 0; u < 32; u++) {
                obc[(size_t)pv[u] * 256] = a2[u];  // bijective: every output written once
            }
        }
    }
}

// ---------------- launch ----------------
extern "C" void kernel_launch(void* const* d_in, const int* in_sizes, int n_in,
                              void* d_out, int out_size) {
    const float* rgb = (const float*)d_in[0];
    const float* ker = (const float*)d_in[1];
    float* out = (float*)d_out;

    perm_kernel<<<128, 256>>>(ker);

    cudaFuncSetAttribute(dct_main, cudaFuncAttributeMaxDynamicSharedMemorySize,
                         TMP_HALFS * (int)sizeof(__half));
    dct_main<<<dim3(2, 16, 32), 256, TMP_HALFS * (int)sizeof(__half)>>>(rgb, out);
}

// round 9
// speedup vs baseline: 1.5083x; 1.2432x over previous
#include <cuda_runtime.h>
#include <cuda_fp16.h>
#include <cstdint>
#include <cstddef>

#define DH __host__ __device__

// ---------------- compile-time DCT constants ----------------
DH constexpr double tcos_core(double x) {
    double x2 = x * x, t = 1.0, s = 1.0;
    for (int i = 1; i <= 12; i++) { t *= -x2 / (double)((2 * i - 1) * (2 * i)); s += t; }
    return s;
}
// cos((2p+1) * f * pi / (2N)) with exact integer reduction.
DH constexpr double dcosg(int f, int p, int N) {
    int m = ((2 * p + 1) * f) % (4 * N);
    double sg = 1.0;
    if (m > 2 * N) m = 4 * N - m;
    if (m > N) { sg = -1.0; m = 2 * N - m; }
    const double PI = 3.14159265358979323846264338327950288;
    return sg * tcos_core((double)m * PI / (2.0 * N));
}
DH constexpr double rsqrt2c() {
    double g = 0.7;
    for (int i = 0; i < 50; i++) g = 0.5 * (g + 0.5 / g);
    return g;
}
// Stage factor: S=0 vertical (fold c_v), S=1 horizontal (fold c_u and 2/32).
DH constexpr double facs(int S, int v) {
    double f = (v == 0) ? rsqrt2c() : 1.0;
    return S ? f * (1.0 / 16.0) : f;
}
// Level-2 split of the 32-point DCT-II:
//  odd v=2w+1 from d;  even-even v=4t from ss (DCT-8);  even-odd v=4t+2 from sd.
DH constexpr float codd(int S, int w, int p) { return (float)(dcosg(2 * w + 1, p, 32) * facs(S, 2 * w + 1)); }
DH constexpr float ceo (int S, int t, int q) { return (float)(dcosg(2 * t + 1, q, 16) * facs(S, 4 * t + 2)); }
DH constexpr float cee (int S, int t, int q) { return (float)(dcosg(t,         q,  8) * facs(S, 4 * t)); }

// ---------------- odd part: 16 inputs d[16] -> 16 accumulators ----------------
template <int S, int P, int W> struct OddW {
    static __device__ __forceinline__ void run(float dv, float (&a)[16]) {
        a[W] = fmaf(dv, codd(S, W, P), a[W]);
        OddW<S, P, W + 1>::run(dv, a);
    }
};
template <int S, int P> struct OddW<S, P, 16> {
    static __device__ __forceinline__ void run(float, float (&)[16]) {}
};
template <int S, int P> struct OddIn {
    static __device__ __forceinline__ void run(const float (&d)[16], float (&a)[16]) {
        OddW<S, P, 0>::run(d[P], a);
        OddIn<S, P + 1>::run(d, a);
    }
};
template <int S> struct OddIn<S, 16> {
    static __device__ __forceinline__ void run(const float (&)[16], float (&)[16]) {}
};

// ---------------- even part: ss[8],sd[8] -> ae[8] (v=4t), ao[8] (v=4t+2) ----------------
template <int S, int Q, int T> struct EvW {
    static __device__ __forceinline__ void run(float ssv, float sdv, float (&ae)[8], float (&ao)[8]) {
        ae[T] = fmaf(ssv, cee(S, T, Q), ae[T]);
        ao[T] = fmaf(sdv, ceo(S, T, Q), ao[T]);
        EvW<S, Q, T + 1>::run(ssv, sdv, ae, ao);
    }
};
template <int S, int Q> struct EvW<S, Q, 8> {
    static __device__ __forceinline__ void run(float, float, float (&)[8], float (&)[8]) {}
};
template <int S, int Q> struct EvIn {
    static __device__ __forceinline__ void run(const float (&ss)[8], const float (&sd)[8],
                                               float (&ae)[8], float (&ao)[8]) {
        EvW<S, Q, 0>::run(ss[Q], sd[Q], ae, ao);
        EvIn<S, Q + 1>::run(ss, sd, ae, ao);
    }
};
template <int S> struct EvIn<S, 8> {
    static __device__ __forceinline__ void run(const float (&)[8], const float (&)[8],
                                               float (&)[8], float (&)[8]) {}
};

// ---------------- permutation derivation from the kernels input ----------------
__device__ int g_pos[1024];  // pos[v*32+u] = output channel index k

__device__ __forceinline__ unsigned long long lanemax_ull(unsigned long long k) {
    #pragma unroll
    for (int o = 16; o; o >>= 1) {
        unsigned long long other = __shfl_xor_sync(0xffffffffu, k, o);
        if (other > k) k = other;
    }
    return k;
}

__global__ void perm_kernel(const float* __restrict__ ker) {
    __shared__ float ctab[32][33];
    int tid = threadIdx.x;
    for (int i = tid; i < 1024; i += 256) {
        int f = i >> 5, x = i & 31;
        ctab[f][x] = cospif((float)((2 * x + 1) * f) * (1.0f / 64.0f));
    }
    __syncthreads();

    int k = blockIdx.x * 8 + (tid >> 5);
    int f = tid & 31;
    const float* K = ker + (size_t)k * 1024;
    float s = 0.f, t = 0.f;
    #pragma unroll
    for (int x = 0; x < 32; x++) {
        float c = ctab[f][x];
        s = fmaf(K[x],      c, s);  // row 0 -> u-score
        t = fmaf(K[x * 32], c, t);  // col 0 -> v-score
    }
    unsigned long long ks = (((unsigned long long)__float_as_uint(fabsf(s))) << 32) | (unsigned)f;
    unsigned long long kt = (((unsigned long long)__float_as_uint(fabsf(t))) << 32) | (unsigned)f;
    ks = lanemax_ull(ks);
    kt = lanemax_ull(kt);
    if (f == 0) {
        g_pos[(int)(kt & 31u) * 32 + (int)(ks & 31u)] = k;
    }
}

// ---------------- main fused kernel ----------------
// Grid: (ng=2, m=16, b=32). CTA = 256 threads, one 32-row x 256-col strip (8 blocks).
// tmp (fp16) planes: [c][v][x] at c*8704 + v*272 + (x/32)*34 + (x%32) halfs
// (34-half group padding: 4B-aligned for half2 loads and bank-conflict-free).
// Stage 1 writes R,G,B vertical-DCT planes; mix pass converts to (2Y,Cb',Cr');
// stage 2 reads a single plane per task.
static constexpr int ROW_HALFS = 272;                 // 8 groups * 34
static constexpr int PLANE_HALFS = 32 * ROW_HALFS;    // 8704
static constexpr int TMP_HALFS = 3 * PLANE_HALFS;     // 26112 halfs = 52224 B
static constexpr int PLANE_H2 = PLANE_HALFS / 2;      // 4352

__global__ void __launch_bounds__(256, 4)
dct_main(const float* __restrict__ rgb, float* __restrict__ out) {
    extern __shared__ __half tmp[];
    __shared__ int pos_s[1024];

    const int tid = threadIdx.x;
    const int ng = blockIdx.x;   // n-group (8 blocks each)
    const int m  = blockIdx.y;   // block row
    const int b  = blockIdx.z;   // batch

    #pragma unroll
    for (int i = 0; i < 4; i++) pos_s[i * 256 + tid] = g_pos[i * 256 + tid];

    // ---- stage 1: per-plane vertical level-2 butterfly DCT. thread = col, loop c. ----
    {
        const size_t plane = (size_t)512 * 512;
        const float* q0 = rgb + (size_t)b * 3 * plane + (size_t)(m * 32) * 512 + ng * 256 + tid;
        const int go = (tid >> 5) * 34 + (tid & 31);

        #pragma unroll 1
        for (int c = 0; c < 3; c++) {
            const float* q = q0 + (size_t)c * plane;
            float s[16], d[16];
            #pragma unroll
            for (int P = 0; P < 16; P++) {
                float lo = q[P * 512], hi = q[(31 - P) * 512];
                s[P] = lo + hi; d[P] = lo - hi;
            }
            __half* tb = tmp + c * PLANE_HALFS + go;

            float ao[16];
            #pragma unroll
            for (int w = 0; w < 16; w++) ao[w] = 0.f;
            OddIn<0, 0>::run(d, ao);
            #pragma unroll
            for (int w = 0; w < 16; w++)
                tb[(2 * w + 1) * ROW_HALFS] = __float2half_rn(ao[w]);

            float ss[8], sd[8];
            #pragma unroll
            for (int q2 = 0; q2 < 8; q2++) { ss[q2] = s[q2] + s[15 - q2]; sd[q2] = s[q2] - s[15 - q2]; }
            float ae[8], ao2[8];
            #pragma unroll
            for (int t = 0; t < 8; t++) { ae[t] = 0.f; ao2[t] = 0.f; }
            EvIn<0, 0>::run(ss, sd, ae, ao2);
            #pragma unroll
            for (int t = 0; t < 8; t++) {
                tb[(4 * t) * ROW_HALFS]     = __float2half_rn(ae[t]);
                tb[(4 * t + 2) * ROW_HALFS] = __float2half_rn(ao2[t]);
            }
        }
    }
    __syncthreads();

    // ---- mix pass (half2-vectorized): RGB planes -> (2Y, Cb', Cr') in place ----
    {
        __half2* t2 = reinterpret_cast<__half2*>(tmp);
        #pragma unroll 1
        for (int i = tid; i < PLANE_H2; i += 256) {
            float2 r2 = __half22float2(t2[i]);
            float2 g2 = __half22float2(t2[PLANE_H2 + i]);
            float2 b2 = __half22float2(t2[2 * PLANE_H2 + i]);
            float y0x = fmaf(0.299f, r2.x, fmaf(0.587f, g2.x, 0.114f * b2.x));
            float y0y = fmaf(0.299f, r2.y, fmaf(0.587f, g2.y, 0.114f * b2.y));
            t2[i]                = __floats2half2_rn(2.0f * y0x, 2.0f * y0y);
            t2[PLANE_H2 + i]     = __floats2half2_rn((b2.x - y0x) * 1.128f, (b2.y - y0y) * 1.128f);
            t2[2 * PLANE_H2 + i] = __floats2half2_rn((r2.x - y0x) * 1.426f, (r2.y - y0y) * 1.426f);
        }
    }
    __syncthreads();

    // ---- stage 2: horizontal level-2 butterfly DCT. thread = (v, nblk), loop c. ----
    {
        const int v = tid >> 3, nblk = tid & 7;
        const int n = ng * 8 + nblk;
        float* ob = out + (((size_t)b * 3072) * 16 + m) * 16 + n;
        const int* pv = pos_s + v * 32;

        #pragma unroll 1
        for (int c = 0; c < 3; c++) {
            const __half2* t2 = reinterpret_cast<const __half2*>(
                tmp + c * PLANE_HALFS + v * ROW_HALFS + nblk * 34);

            float vals[32];
            #pragma unroll
            for (int j = 0; j < 16; j++) {
                float2 f2 = __half22float2(t2[j]);
                vals[2 * j] = f2.x; vals[2 * j + 1] = f2.y;
            }
            float s[16], d[16];
            #pragma unroll
            for (int P = 0; P < 16; P++) {
                s[P] = vals[P] + vals[31 - P];
                d[P] = vals[P] - vals[31 - P];
            }

            float* obc = ob + (size_t)c * 1024 * 256;

            float ao[16];
            #pragma unroll
            for (int w = 0; w < 16; w++) ao[w] = 0.f;
            OddIn<1, 0>::run(d, ao);
            #pragma unroll
            for (int w = 0; w < 16; w++)
                obc[(size_t)pv[2 * w + 1] * 256] = ao[w];

            float ss[8], sd[8];
            #pragma unroll
            for (int q2 = 0; q2 < 8; q2++) { ss[q2] = s[q2] + s[15 - q2]; sd[q2] = s[q2] - s[15 - q2]; }
            float ae[8], ao2[8];
            #pragma unroll
            for (int t = 0; t < 8; t++) { ae[t] = 0.f; ao2[t] = 0.f; }
            EvIn<1, 0>::run(ss, sd, ae, ao2);

            if (c == 0 && v == 0) ae[0] -= 32.0f;   // DC term of the "-1" offset

            #pragma unroll
            for (int t = 0; t < 8; t++) {
                obc[(size_t)pv[4 * t] * 256]     = ae[t];
                obc[(size_t)pv[4 * t + 2] * 256] = ao2[t];
            }
        }
    }
}

// ---------------- launch ----------------
extern "C" void kernel_launch(void* const* d_in, const int* in_sizes, int n_in,
                              void* d_out, int out_size) {
    const float* rgb = (const float*)d_in[0];
    const float* ker = (const float*)d_in[1];
    float* out = (float*)d_out;

    perm_kernel<<<128, 256>>>(ker);

    cudaFuncSetAttribute(dct_main, cudaFuncAttributeMaxDynamicSharedMemorySize,
                         TMP_HALFS * (int)sizeof(__half));
    dct_main<<<dim3(2, 16, 32), 256, TMP_HALFS * (int)sizeof(__half)>>>(rgb, out);
}